// round 10
// baseline (speedup 1.0000x reference)
#include <cuda_runtime.h>
#include <cuda_bf16.h>
#include <math.h>

#define NBINS    256
#define WARPS    12
#define THREADS  (WARPS * 32)           // 384
#define GRID     148                    // one CTA per SM
#define STRIDE_HW 34                    // halfwords per bin row (pad: 17 coprime 32)
#define REG_HW   (NBINS * STRIDE_HW)    // 8704 halfwords = 17408 B per warp
#define DYN_SMEM (WARPS * REG_HW * 2)   // 208896 bytes

__device__ unsigned int g_hist[NBINS];   // zero-initialized at module load
__device__ unsigned int g_ticket;        // zero-initialized at module load

__device__ __forceinline__ int bin_of(float f) {
    const float scale = 1.00392156862745097e+00f;   // rn(256/255)
    int idx = (int)(f * scale);                      // trunc==floor, f>=0
    return min(idx, NBINS - 1);
}

// pairwise RMW on lane-private uint16 counters: loads precede stores, so the
// two chains are independent when a!=b (guaranteed by inc/predication logic).
__device__ __forceinline__ void rmw_pair(unsigned short* __restrict__ my,
                                         float f0, float f1) {
    int a = bin_of(f0);
    int b = bin_of(f1);
    unsigned short x = my[a * STRIDE_HW];
    unsigned short y = my[b * STRIDE_HW];
    unsigned short incx = (a == b) ? (unsigned short)2 : (unsigned short)1;
    my[a * STRIDE_HW] = (unsigned short)(x + incx);
    if (a != b) my[b * STRIDE_HW] = (unsigned short)(y + 1);
}

__global__ __launch_bounds__(THREADS, 1)
void hist_kernel(const float* __restrict__ x, int n,
                 const void* __restrict__ bs_ptr, float* __restrict__ out) {
    extern __shared__ unsigned short cnt[];          // WARPS * REG_HW halfwords
    __shared__ unsigned int s_is_last;

    const int tid  = threadIdx.x;
    const int lane = tid & 31;
    const int warp = tid >> 5;

    // zero 204 KB as uint4
    {
        uint4 z = make_uint4(0u, 0u, 0u, 0u);
        uint4* p = (uint4*)cnt;
        const int nv = DYN_SMEM / 16;                // 13056
        for (int i = tid; i < nv; i += THREADS) p[i] = z;
    }
    __syncthreads();

    // lane-private base: element (bin) lives at my[bin*34]
    unsigned short* my = cnt + warp * REG_HW + lane;

    const int n4 = n >> 2;
    const float4* __restrict__ x4 = (const float4*)x;
    const int stride = GRID * THREADS;               // 56832
    const int gid = blockIdx.x * THREADS + tid;

    const int span   = 4 * stride;                   // 4 float4 per iteration
    const int n_full = (n4 / span) * span;

    // main loop: 4 front-batched LDG.128 (16 elements = 8 RMW pairs)
    for (int base = gid; base < n_full; base += span) {
        float4 v0 = x4[base];
        float4 v1 = x4[base + stride];
        float4 v2 = x4[base + 2 * stride];
        float4 v3 = x4[base + 3 * stride];

        rmw_pair(my, v0.x, v0.y);  rmw_pair(my, v0.z, v0.w);
        rmw_pair(my, v1.x, v1.y);  rmw_pair(my, v1.z, v1.w);
        rmw_pair(my, v2.x, v2.y);  rmw_pair(my, v2.z, v2.w);
        rmw_pair(my, v3.x, v3.y);  rmw_pair(my, v3.z, v3.w);
    }

    // float4 tail (~0.9 iterations/thread)
    for (int i = n_full + gid; i < n4; i += stride) {
        float4 v = x4[i];
        rmw_pair(my, v.x, v.y);
        rmw_pair(my, v.z, v.w);
    }

    // scalar tail (n % 4)
    for (int i = (n4 << 2) + gid; i < n; i += stride) {
        int a = bin_of(x[i]);
        unsigned short xv = my[a * STRIDE_HW];
        my[a * STRIDE_HW] = (unsigned short)(xv + 1);
    }

    __syncthreads();

    // merge: thread b (b < 256) sums 12 warps x 32 lanes of uint16 for bin b.
    // Read as uint32: region w at word offset w*(REG_HW/2), bin row = 17 words.
    // Across a merge warp (32 consecutive bins), bank = (17*b + j) % 32 is a
    // bijection in b -> conflict-free.
    if (tid < NBINS) {
        const unsigned int* c32 = (const unsigned int*)cnt;
        unsigned int total = 0;
        #pragma unroll
        for (int w = 0; w < WARPS; w++) {
            const unsigned int* row = c32 + w * (REG_HW / 2) + tid * (STRIDE_HW / 2);
            #pragma unroll
            for (int j = 0; j < STRIDE_HW / 2; j++) {   // 17 words = 34 halfwords
                unsigned int u = row[j];
                total += (u & 0xFFFFu) + (u >> 16);
            }
        }
        if (total) atomicAdd(&g_hist[tid], total);
    }

    // ---- fused finalize: last CTA does the epilogue ----
    __threadfence();
    __syncthreads();
    if (tid == 0)
        s_is_last = (atomicAdd(&g_ticket, 1u) == (unsigned)(GRID - 1));
    __syncthreads();

    if (s_is_last) {
        __threadfence();                 // acquire: see all g_hist atomics
        if (tid < NBINS) {
            unsigned int hv = g_hist[tid];
            unsigned int h0 = g_hist[0];

            // batchsize dtype sniff: int32 small value vs float32 bit pattern
            int iv = *(const int*)bs_ptr;
            float bs = (iv >= 0 && iv < (1 << 24)) ? (float)iv
                                                   : *(const float*)bs_ptr;

            out[tid]         = (float)hv;
            out[NBINS + tid] = bs * (float)h0;
        }
        __syncthreads();                 // all reads of g_hist done
        if (tid < NBINS) g_hist[tid] = 0u;   // reset for next graph replay
        if (tid == 0) g_ticket = 0u;
    }
}

extern "C" void kernel_launch(void* const* d_in, const int* in_sizes, int n_in,
                              void* d_out, int out_size) {
    int img_idx = 0, bs_idx = 1;
    if (n_in >= 2) {
        if (in_sizes[0] >= in_sizes[1]) { img_idx = 0; bs_idx = 1; }
        else                            { img_idx = 1; bs_idx = 0; }
    }
    const float* x = (const float*)d_in[img_idx];
    const void* bs = d_in[bs_idx];
    int n = in_sizes[img_idx];

    static bool attr_set = false;
    if (!attr_set) {
        cudaFuncSetAttribute(hist_kernel,
                             cudaFuncAttributeMaxDynamicSharedMemorySize,
                             DYN_SMEM);
        attr_set = true;
    }

    hist_kernel<<<GRID, THREADS, DYN_SMEM>>>(x, n, bs, (float*)d_out);
}

// round 13
// speedup vs baseline: 1.5452x; 1.5452x over previous
#include <cuda_runtime.h>
#include <cuda_bf16.h>
#include <math.h>

#define NBINS   256
#define NWORDS  64             // 4 byte-packed bins per 32-bit word
#define NCOPIES 8              // one packed sub-histogram per warp
#define THREADS 256
#define CTAS_PER_SM 4
#define BLOCKS  (148 * CTAS_PER_SM)   // 592
#define BATCH   8

__device__ unsigned int g_hist[NBINS];   // zero-initialized at module load
__device__ unsigned int g_ticket;        // zero-initialized at module load

__global__ __launch_bounds__(THREADS, CTAS_PER_SM)
void hist_kernel(const float* __restrict__ x, int n,
                 const void* __restrict__ bs_ptr, float* __restrict__ out) {
    __shared__ unsigned int sh[NCOPIES][NWORDS];   // 2 KB
    __shared__ unsigned int s_is_last;

    const int tid  = threadIdx.x;
    const int warp = tid >> 5;

    // BUGFIX (R11/R12): zero ALL 512 words, not just the first 256.
    #pragma unroll
    for (int i = tid; i < NCOPIES * NWORDS; i += THREADS)
        ((unsigned int*)sh)[i] = 0u;
    __syncthreads();

    unsigned int* myhist = sh[warp];
    const float scale = 1.00392156862745097e+00f;   // rn(256/255)

    const int n4 = n >> 2;
    const float4* __restrict__ x4 = (const float4*)x;
    const int stride = BLOCKS * THREADS;             // 151552
    const int gid = blockIdx.x * THREADS + tid;

    const int batch_span = BATCH * stride;
    const int n_full     = (n4 / batch_span) * batch_span;

    // main: unpredicated 8x LDG.128 batches (87% of data)
    for (int base = gid; base < n_full; base += batch_span) {
        float4 v[BATCH];
        #pragma unroll
        for (int u = 0; u < BATCH; u++)
            v[u] = x4[base + u * stride];
        #pragma unroll
        for (int u = 0; u < BATCH; u++) {
            #pragma unroll
            for (int k = 0; k < 4; k++) {
                float f = (k == 0) ? v[u].x : (k == 1) ? v[u].y
                        : (k == 2) ? v[u].z : v[u].w;
                int idx = (int)(f * scale);          // trunc==floor, f>=0
                idx = min(idx, NBINS - 1);           // f==255.0 -> last bin
                // byte-packed: 4 bins/word reduces distinct atomic addresses
                atomicAdd(&myhist[idx >> 2], 1u << ((idx & 3) << 3));
            }
        }
    }

    // float4 tail
    for (int i = n_full + gid; i < n4; i += stride) {
        float4 v = x4[i];
        #pragma unroll
        for (int k = 0; k < 4; k++) {
            float f = (k == 0) ? v.x : (k == 1) ? v.y : (k == 2) ? v.z : v.w;
            int idx = (int)(f * scale);
            idx = min(idx, NBINS - 1);
            atomicAdd(&myhist[idx >> 2], 1u << ((idx & 3) << 3));
        }
    }

    // scalar tail (n % 4)
    for (int i = (n4 << 2) + gid; i < n; i += stride) {
        float f = x[i];
        int idx = (int)(f * scale);
        idx = min(idx, NBINS - 1);
        atomicAdd(&myhist[idx >> 2], 1u << ((idx & 3) << 3));
    }

    __syncthreads();

    // merge: thread b extracts byte field (b&3) of word (b>>2) from 8 copies
    {
        const int w   = tid >> 2;
        const int sh8 = (tid & 3) << 3;
        unsigned int total = 0;
        #pragma unroll
        for (int c = 0; c < NCOPIES; c++)
            total += (sh[c][w] >> sh8) & 0xFFu;
        atomicAdd(&g_hist[tid], total);
    }

    // ---- fused finalize: last CTA does the epilogue ----
    __threadfence();
    __syncthreads();
    if (tid == 0)
        s_is_last = (atomicAdd(&g_ticket, 1u) == (unsigned)(BLOCKS - 1));
    __syncthreads();

    if (s_is_last) {
        __threadfence();                 // acquire: see all g_hist atomics
        unsigned int hv = g_hist[tid];
        unsigned int h0 = g_hist[0];

        // batchsize dtype sniff: int32 small value vs float32 bit pattern
        int iv = *(const int*)bs_ptr;
        float bs = (iv >= 0 && iv < (1 << 24)) ? (float)iv
                                               : *(const float*)bs_ptr;

        out[tid]         = (float)hv;
        out[NBINS + tid] = bs * (float)h0;

        __syncthreads();                 // all reads of g_hist done
        g_hist[tid] = 0u;                // reset for next graph replay
        if (tid == 0) g_ticket = 0u;
    }
}

extern "C" void kernel_launch(void* const* d_in, const int* in_sizes, int n_in,
                              void* d_out, int out_size) {
    int img_idx = 0, bs_idx = 1;
    if (n_in >= 2) {
        if (in_sizes[0] >= in_sizes[1]) { img_idx = 0; bs_idx = 1; }
        else                            { img_idx = 1; bs_idx = 0; }
    }
    const float* x = (const float*)d_in[img_idx];
    const void* bs = d_in[bs_idx];
    int n = in_sizes[img_idx];

    hist_kernel<<<BLOCKS, THREADS>>>(x, n, bs, (float*)d_out);
}